// round 5
// baseline (speedup 1.0000x reference)
#include <cuda_runtime.h>

// ---------------------------------------------------------------------------
// WaveNet Mel2Raw — tf32 mma.sync, permuted n-tiles for fully vectorized
// smem B loads (LDS.128) and float4 epilogues/staging.
// ---------------------------------------------------------------------------

namespace {

constexpr int Bn  = 2;
constexpr int Ln  = 32512;
constexpr int Rn  = 64;
constexpr int Sn  = 128;
constexpr int NMn = 80;
constexpr int NCn = 256;
constexpr int NBn = 30;

constexpr int AP = 136;   // smem pitch (x4B); rows 16B-aligned (136*4 % 16 == 0)
constexpr int PP = 136;

// ---- packed tf32 weight buffer (A fragments) ----
constexpr int PK_DIL_BLK  = 16384;
constexpr int PK_DIL_TAP  = 8192;
constexpr int OFF_DIL     = 0;
constexpr int PK_COND_BLK = 10240;
constexpr int OFF_COND    = 491520;
constexpr int PK_SKIP_BLK = 8192;
constexpr int OFF_SKIP    = 798720;
constexpr int PK_RES_BLK  = 4096;
constexpr int OFF_RES     = 1044480;
constexpr int OFF_P1      = 1167360;
constexpr int OFF_P2      = 1200128;
constexpr int PK_TOTAL    = 1265664;

__device__ unsigned g_pk[PK_TOTAL];

__device__ float g_cond[Bn * NMn * Ln];
__device__ float g_resA[Bn * Rn  * Ln];
__device__ float g_resB[Bn * Rn  * Ln];
__device__ float g_skip[Bn * Sn  * Ln];
__device__ float g_y1  [Bn * NCn * Ln];

__device__ __forceinline__ float ex2f(float x) {
    float y; asm("ex2.approx.f32 %0, %1;" : "=f"(y) : "f"(x)); return y;
}
__device__ __forceinline__ float rcpf(float x) {
    float y; asm("rcp.approx.f32 %0, %1;" : "=f"(y) : "f"(x)); return y;
}
__device__ __forceinline__ float gate_fn(float f, float g) {
    float ef = ex2f(2.8853900817779268f * f);
    float th = 1.0f - 2.0f * rcpf(ef + 1.0f);
    float sg = rcpf(1.0f + ex2f(-1.4426950408889634f * g));
    return th * sg;
}
__device__ __forceinline__ unsigned f2tf(float x) {
    unsigned u; asm("cvt.rna.tf32.f32 %0, %1;" : "=r"(u) : "f"(x)); return u;
}

__device__ __forceinline__ void mma8(float c[4], const unsigned a[4], const unsigned b[2]) {
    asm volatile(
        "mma.sync.aligned.m16n8k8.row.col.f32.tf32.tf32.f32 "
        "{%0,%1,%2,%3},{%4,%5,%6,%7},{%8,%9},{%0,%1,%2,%3};"
        : "+f"(c[0]), "+f"(c[1]), "+f"(c[2]), "+f"(c[3])
        : "r"(a[0]), "r"(a[1]), "r"(a[2]), "r"(a[3]), "r"(b[0]), "r"(b[1]));
}

// pick float4 from acc plane: {a[jb..jb+3][idx]}
__device__ __forceinline__ float4 pick4(const float (*a)[4], int jb, int idx) {
    float4 v; v.x = a[jb][idx]; v.y = a[jb+1][idx]; v.z = a[jb+2][idx]; v.w = a[jb+3][idx];
    return v;
}
__device__ __forceinline__ uint4 gate4(const float (*f)[4], const float (*g)[4], int jb, int idx) {
    uint4 v;
    v.x = f2tf(gate_fn(f[jb  ][idx], g[jb  ][idx]));
    v.y = f2tf(gate_fn(f[jb+1][idx], g[jb+1][idx]));
    v.z = f2tf(gate_fn(f[jb+2][idx], g[jb+2][idx]));
    v.w = f2tf(gate_fn(f[jb+3][idx], g[jb+3][idx]));
    return v;
}

// Two M-16 tiles, warp N tile = 64 (permuted n-tiles: tile j covers times n0+8c+j).
// B vector loads: thread gid reads 8 consecutive values at [row][n0+8*gid].
__device__ __forceinline__ void gemm_p2s(
    float acc[2][8][4], const unsigned* __restrict__ sB, int pitch,
    int rowbase, int nk, const uint4* __restrict__ pkA, int miStride,
    int lane, int n0, int gid, int tig)
{
    #pragma unroll
    for (int ks = 0; ks < nk; ks++) {
        uint4 va0 = pkA[ks * 32 + lane];
        uint4 va1 = pkA[miStride + ks * 32 + lane];
        unsigned A0[4] = {va0.x, va0.y, va0.z, va0.w};
        unsigned A1[4] = {va1.x, va1.y, va1.z, va1.w};
        const unsigned* base = sB + (rowbase + ks * 8 + tig) * pitch + n0 + 8 * gid;
        uint4 b0lo = *(const uint4*)base;
        uint4 b0hi = *(const uint4*)(base + 4);
        uint4 b1lo = *(const uint4*)(base + 4 * pitch);
        uint4 b1hi = *(const uint4*)(base + 4 * pitch + 4);
        unsigned B0[8] = {b0lo.x, b0lo.y, b0lo.z, b0lo.w, b0hi.x, b0hi.y, b0hi.z, b0hi.w};
        unsigned B1[8] = {b1lo.x, b1lo.y, b1lo.z, b1lo.w, b1hi.x, b1hi.y, b1hi.z, b1hi.w};
        #pragma unroll
        for (int j = 0; j < 8; j++) {
            unsigned bf[2] = { B0[j], B1[j] };
            mma8(acc[0][j], A0, bf);
            mma8(acc[1][j], A1, bf);
        }
    }
}

// Single M-16 tile.
__device__ __forceinline__ void gemm_p1v(
    float acc[8][4], const unsigned* __restrict__ sB, int pitch,
    int nk, const uint4* __restrict__ pkA,
    int lane, int n0, int gid, int tig)
{
    #pragma unroll
    for (int ks = 0; ks < nk; ks++) {
        uint4 va = pkA[ks * 32 + lane];
        unsigned A[4] = {va.x, va.y, va.z, va.w};
        const unsigned* base = sB + (ks * 8 + tig) * pitch + n0 + 8 * gid;
        uint4 b0lo = *(const uint4*)base;
        uint4 b0hi = *(const uint4*)(base + 4);
        uint4 b1lo = *(const uint4*)(base + 4 * pitch);
        uint4 b1hi = *(const uint4*)(base + 4 * pitch + 4);
        unsigned B0[8] = {b0lo.x, b0lo.y, b0lo.z, b0lo.w, b0hi.x, b0hi.y, b0hi.z, b0hi.w};
        unsigned B1[8] = {b1lo.x, b1lo.y, b1lo.z, b1lo.w, b1hi.x, b1hi.y, b1hi.z, b1hi.w};
        #pragma unroll
        for (int j = 0; j < 8; j++) {
            unsigned bf[2] = { B0[j], B1[j] };
            mma8(acc[j], A, bf);
        }
    }
}

// ---------------------------------------------------------------------------
// prep: pack weights into tf32 A-fragment order
// ---------------------------------------------------------------------------
__device__ __forceinline__ uint4 pack_frag(const float* __restrict__ src,
                                           int as, int am, int ao,
                                           int nk, int idx4)
{
    const int mt   = idx4 / (nk * 32);
    const int rem  = idx4 % (nk * 32);
    const int ks   = rem >> 5;
    const int lane = rem & 31;
    const int gid  = lane >> 2, tig = lane & 3;
    const int r = mt * 16 + gid;
    const int k = ks * 8 + tig;
    uint4 v;
    v.x = f2tf(src[r * as + k * am + ao]);
    v.y = f2tf(src[(r + 8) * as + k * am + ao]);
    v.z = f2tf(src[r * as + (k + 4) * am + ao]);
    v.w = f2tf(src[(r + 8) * as + (k + 4) * am + ao]);
    return v;
}

__global__ void prep_kernel(
    const float* __restrict__ dil_w,  const float* __restrict__ cond_w,
    const float* __restrict__ skip_w, const float* __restrict__ res_w,
    const float* __restrict__ p1_w,   const float* __restrict__ p2_w)
{
    uint4* pk = (uint4*)g_pk;
    const int stride = gridDim.x * blockDim.x;
    for (int q = blockIdx.x * blockDim.x + threadIdx.x; q < PK_TOTAL / 4; q += stride) {
        uint4 v;
        if (q < OFF_COND / 4) {
            const int blk = q / (PK_DIL_BLK / 4), r2 = q % (PK_DIL_BLK / 4);
            const int tap = r2 / (PK_DIL_TAP / 4), idx4 = r2 % (PK_DIL_TAP / 4);
            v = pack_frag(dil_w + blk * 16384, 128, 2, tap, 8, idx4);
        } else if (q < OFF_SKIP / 4) {
            const int q2 = q - OFF_COND / 4;
            const int blk = q2 / (PK_COND_BLK / 4), idx4 = q2 % (PK_COND_BLK / 4);
            v = pack_frag(cond_w + blk * (128 * NMn), NMn, 1, 0, 10, idx4);
        } else if (q < OFF_RES / 4) {
            const int q2 = q - OFF_SKIP / 4;
            const int blk = q2 / (PK_SKIP_BLK / 4), idx4 = q2 % (PK_SKIP_BLK / 4);
            v = pack_frag(skip_w + blk * (Sn * Rn), 64, 1, 0, 8, idx4);
        } else if (q < OFF_P1 / 4) {
            const int q2 = q - OFF_RES / 4;
            const int blk = q2 / (PK_RES_BLK / 4), idx4 = q2 % (PK_RES_BLK / 4);
            v = pack_frag(res_w + blk * (Rn * Rn), 64, 1, 0, 8, idx4);
        } else if (q < OFF_P2 / 4) {
            v = pack_frag(p1_w, 128, 1, 0, 16, q - OFF_P1 / 4);
        } else {
            v = pack_frag(p2_w, 256, 1, 0, 32, q - OFF_P2 / 4);
        }
        pk[q] = v;
    }
}

// ---------------------------------------------------------------------------
__global__ __launch_bounds__(256) void cond_kernel(
    const float* __restrict__ mels, const float* __restrict__ mel_w,
    const float* __restrict__ mel_b)
{
    __shared__ float m0s[NMn], m1s[NMn];
    const int b  = blockIdx.y;
    const int t0 = blockIdx.x * 128;
    const int q  = t0 >> 8;
    const int tid = threadIdx.x;
    if (tid < NMn) {
        m0s[tid] = mels[(b * NMn + tid) * 128 + q];
        m1s[tid] = mels[(b * NMn + tid) * 128 + q + 1];
    }
    __syncthreads();
    for (int j = tid; j < NMn * 128; j += 256) {
        const int c  = j >> 7;
        const int tt = j & 127;
        const int t  = t0 + tt;
        const int r  = t & 255;
        const float* w = mel_w + c * (NMn * 512);
        float acc = mel_b[c];
        #pragma unroll 4
        for (int ci = 0; ci < NMn; ci++) {
            acc += w[ci * 512 + 255 - r] * m0s[ci];
            acc += w[ci * 512 + 511 - r] * m1s[ci];
        }
        g_cond[(b * NMn + c) * Ln + t] = acc;
    }
}

__global__ void init_kernel(const float* __restrict__ x,
                            const float* __restrict__ iw,
                            const float* __restrict__ ib)
{
    const int stride = gridDim.x * blockDim.x;
    const int tid0   = blockIdx.x * blockDim.x + threadIdx.x;
    for (int i = tid0; i < Bn * Rn * Ln; i += stride) {
        const int t = i % Ln;
        const int r = (i / Ln) % Rn;
        const int b = i / (Ln * Rn);
        g_resA[i] = iw[r] * x[b * Ln + t] + ib[r];
    }
    for (int i = tid0; i < Bn * Sn * Ln; i += stride) g_skip[i] = 0.0f;
}

// ---------------------------------------------------------------------------
// Fused block kernel: 256 threads, 8 warps (4M x 2N), tile 128co x 128t
// ---------------------------------------------------------------------------
constexpr int BLK_SMEM = 208 * AP * 4;   // 113152 B -> 2 CTAs/SM

__global__ __launch_bounds__(256, 2) void block_kernel(
    const float* __restrict__ dil_b, const float* __restrict__ cond_b,
    const float* __restrict__ skip_b, const float* __restrict__ res_b,
    const float* __restrict__ res_in, float* __restrict__ res_out,
    int blk)
{
    extern __shared__ unsigned smu[];
    unsigned* s_act = smu;                     // rows: 0-63 prev, 64-127 cur, 128-207 cond
    unsigned* s_h   = smu;                     // rows 0-63 reused for h (tf32)
    float*    s_st  = (float*)(smu + 64 * AP); // rows 64-191 reused: skip staging [128][AP]

    const int d = 1 << (blk % 10);
    const float* bd = dil_b  + blk * 128;
    const float* bc = cond_b + blk * 128;
    const float* bs = skip_b + blk * Sn;
    const float* br = res_b  + blk * Rn;

    const int b   = blockIdx.y;
    const int t0  = blockIdx.x * 128;
    const int tid = threadIdx.x;

    // ---- stage activations (vectorized) ----
    const float* resb = res_in + b * (Rn * Ln);
    for (int i = tid; i < 64 * 32; i += 256) {
        const int ci = i >> 5, v = (i & 31) * 4;
        float4 cv = *(const float4*)(resb + ci * Ln + t0 + v);
        uint4 s; s.x = f2tf(cv.x); s.y = f2tf(cv.y); s.z = f2tf(cv.z); s.w = f2tf(cv.w);
        *(uint4*)(s_act + (64 + ci) * AP + v) = s;
    }
    if ((d & 3) == 0) {
        for (int i = tid; i < 64 * 32; i += 256) {
            const int ci = i >> 5, v = (i & 31) * 4;
            const int tp = t0 - d + v;
            uint4 s;
            if (tp >= 0) {
                float4 pv = *(const float4*)(resb + ci * Ln + tp);
                s.x = f2tf(pv.x); s.y = f2tf(pv.y); s.z = f2tf(pv.z); s.w = f2tf(pv.w);
            } else { s.x = s.y = s.z = s.w = 0u; }
            *(uint4*)(s_act + ci * AP + v) = s;
        }
    } else {
        for (int i = tid; i < 64 * 128; i += 256) {
            const int ci = i >> 7, tt = i & 127;
            const int tp = t0 + tt - d;
            const float pv = (tp >= 0) ? resb[ci * Ln + tp] : 0.0f;
            s_act[ci * AP + tt] = f2tf(pv);
        }
    }
    const float* condb = g_cond + b * (NMn * Ln);
    for (int i = tid; i < NMn * 32; i += 256) {
        const int ci = i >> 5, v = (i & 31) * 4;
        float4 cv = *(const float4*)(condb + ci * Ln + t0 + v);
        uint4 s; s.x = f2tf(cv.x); s.y = f2tf(cv.y); s.z = f2tf(cv.z); s.w = f2tf(cv.w);
        *(uint4*)(s_act + (128 + ci) * AP + v) = s;
    }
    __syncthreads();

    const int lane = tid & 31, warp = tid >> 5;
    const int gid = lane >> 2, tig = lane & 3;
    const int mw = warp & 3;
    const int n0 = (warp >> 2) * 64;
    const int m0f = mw * 16;
    const int cb = n0 + 16 * tig;    // thread's 16 consecutive output columns

    // ---- GEMM1: acc[0] = f rows, acc[1] = g rows ----
    float acc[2][8][4];
    {
        const int rf = m0f + gid, rg = rf + 64;
        const float f0 = bd[rf] + bc[rf],       f1 = bd[rf + 8] + bc[rf + 8];
        const float g0 = bd[rg] + bc[rg],       g1 = bd[rg + 8] + bc[rg + 8];
        #pragma unroll
        for (int j = 0; j < 8; j++) {
            acc[0][j][0] = f0; acc[0][j][1] = f0; acc[0][j][2] = f1; acc[0][j][3] = f1;
            acc[1][j][0] = g0; acc[1][j][1] = g0; acc[1][j][2] = g1; acc[1][j][3] = g1;
        }
    }
    const uint4* pk_dil = (const uint4*)(g_pk + OFF_DIL + blk * PK_DIL_BLK);
    const uint4* pk_c   = (const uint4*)(g_pk + OFF_COND + blk * PK_COND_BLK);
    gemm_p2s(acc, s_act, AP,   0,  8, pk_dil + mw * 256,        4 * 256, lane, n0, gid, tig);
    gemm_p2s(acc, s_act, AP,  64,  8, pk_dil + 2048 + mw * 256, 4 * 256, lane, n0, gid, tig);
    gemm_p2s(acc, s_act, AP, 128, 10, pk_c + mw * 320,          4 * 320, lane, n0, gid, tig);

    __syncthreads();   // all GEMM1 smem reads complete

    // ---- gate in registers -> h (tf32) rows 0-63, vectorized stores ----
    {
        const int r0 = m0f + gid, r1 = r0 + 8;
        uint4* hr0 = (uint4*)(s_h + r0 * AP + cb);
        hr0[0] = gate4(acc[0], acc[1], 0, 0);
        hr0[1] = gate4(acc[0], acc[1], 4, 0);
        hr0[2] = gate4(acc[0], acc[1], 0, 1);
        hr0[3] = gate4(acc[0], acc[1], 4, 1);
        uint4* hr1 = (uint4*)(s_h + r1 * AP + cb);
        hr1[0] = gate4(acc[0], acc[1], 0, 2);
        hr1[1] = gate4(acc[0], acc[1], 4, 2);
        hr1[2] = gate4(acc[0], acc[1], 0, 3);
        hr1[3] = gate4(acc[0], acc[1], 4, 3);
    }
    __syncthreads();

    // ---- GEMM2: skip contribution (M=128, K=64) ----
    const int m0s = mw * 32;
    {
        const int r0 = m0s + gid;
        const float z0 = bs[r0], z1 = bs[r0 + 8];
        const float z2 = bs[r0 + 16], z3 = bs[r0 + 24];
        #pragma unroll
        for (int j = 0; j < 8; j++) {
            acc[0][j][0] = z0; acc[0][j][1] = z0; acc[0][j][2] = z1; acc[0][j][3] = z1;
            acc[1][j][0] = z2; acc[1][j][1] = z2; acc[1][j][2] = z3; acc[1][j][3] = z3;
        }
    }
    const uint4* pk_s = (const uint4*)(g_pk + OFF_SKIP + blk * PK_SKIP_BLK);
    gemm_p2s(acc, s_h, AP, 0, 8, pk_s + (m0s >> 4) * 256, 256, lane, n0, gid, tig);

    // stage skip acc into rows 64-191, vectorized
    #pragma unroll
    for (int mi = 0; mi < 2; mi++) {
        const int r0 = m0s + mi * 16 + gid;
        float* p0 = s_st + r0 * AP + cb;
        *(float4*)(p0)      = pick4(acc[mi], 0, 0);
        *(float4*)(p0 + 4)  = pick4(acc[mi], 4, 0);
        *(float4*)(p0 + 8)  = pick4(acc[mi], 0, 1);
        *(float4*)(p0 + 12) = pick4(acc[mi], 4, 1);
        float* p1 = s_st + (r0 + 8) * AP + cb;
        *(float4*)(p1)      = pick4(acc[mi], 0, 2);
        *(float4*)(p1 + 4)  = pick4(acc[mi], 4, 2);
        *(float4*)(p1 + 8)  = pick4(acc[mi], 0, 3);
        *(float4*)(p1 + 12) = pick4(acc[mi], 4, 3);
    }
    __syncthreads();

    // ---- coalesced skip RMW ----
    {
        float* skb = g_skip + b * (Sn * Ln) + t0;
        for (int i = tid; i < 128 * 32; i += 256) {
            const int row = i >> 5, q = (i & 31) * 4;
            const float4 a4 = *(const float4*)(s_st + row * AP + q);
            float4* gp = (float4*)(skb + row * Ln + q);
            float4 v = *gp;
            v.x += a4.x; v.y += a4.y; v.z += a4.z; v.w += a4.w;
            *gp = v;
        }
    }

    // ---- GEMM3: res_out = res_in + Wr*h + br (M=64, K=64) ----
    float accr[8][4];
    const int mr = mw * 16;
    {
        const int r0 = mr + gid;
        const float z0 = br[r0], z1 = br[r0 + 8];
        #pragma unroll
        for (int j = 0; j < 8; j++) {
            accr[j][0] = z0; accr[j][1] = z0;
            accr[j][2] = z1; accr[j][3] = z1;
        }
    }
    const uint4* pk_r = (const uint4*)(g_pk + OFF_RES + blk * PK_RES_BLK);
    gemm_p1v(accr, s_h, AP, 8, pk_r + (mr >> 4) * 256, lane, n0, gid, tig);

    {
        float* rob = res_out + b * (Rn * Ln) + t0;
        const float* rib = resb + t0;
        const int r0 = mr + gid;
        #pragma unroll
        for (int half = 0; half < 2; half++) {
            const int r = r0 + half * 8;
            const float* pi = rib + r * Ln + cb;
            float* po = rob + r * Ln + cb;
            #pragma unroll
            for (int qq = 0; qq < 4; qq++) {
                const int jb = (qq & 1) * 4, idx = half * 2 + (qq >> 1);
                float4 a4 = pick4(accr, jb, idx);
                float4 iv = *(const float4*)(pi + qq * 4);
                iv.x += a4.x; iv.y += a4.y; iv.z += a4.z; iv.w += a4.w;
                *(float4*)(po + qq * 4) = iv;
            }
        }
    }
}

// ---------------------------------------------------------------------------
// post1: 512 threads, 16 warps (8M x 2N), tile 256co x 128t, K=128
// ---------------------------------------------------------------------------
constexpr int P1_SMEM = 128 * PP * 4;

__global__ __launch_bounds__(512, 1) void p1_kernel(const float* __restrict__ b1)
{
    extern __shared__ unsigned smu[];
    unsigned* s_a = smu;
    const int b = blockIdx.y, t0 = blockIdx.x * 128, tid = threadIdx.x;

    const float* skb = g_skip + b * (Sn * Ln);
    for (int i = tid; i < 128 * 32; i += 512) {
        const int ci = i >> 5, v = (i & 31) * 4;
        float4 x = *(const float4*)(skb + ci * Ln + t0 + v);
        uint4 s;
        s.x = f2tf(fmaxf(x.x, 0.0f)); s.y = f2tf(fmaxf(x.y, 0.0f));
        s.z = f2tf(fmaxf(x.z, 0.0f)); s.w = f2tf(fmaxf(x.w, 0.0f));
        *(uint4*)(s_a + ci * PP + v) = s;
    }
    __syncthreads();

    const int lane = tid & 31, warp = tid >> 5;
    const int gid = lane >> 2, tig = lane & 3;
    const int m0 = (warp & 7) * 32, n0 = (warp >> 3) * 64;
    const int cb = n0 + 16 * tig;

    float acc[2][8][4];
    #pragma unroll
    for (int mi = 0; mi < 2; mi++) {
        const int r0 = m0 + mi * 16 + gid;
        const float z0 = b1[r0], z1 = b1[r0 + 8];
        #pragma unroll
        for (int j = 0; j < 8; j++) {
            acc[mi][j][0] = z0; acc[mi][j][1] = z0;
            acc[mi][j][2] = z1; acc[mi][j][3] = z1;
        }
    }
    const uint4* pk = (const uint4*)(g_pk + OFF_P1);
    gemm_p2s(acc, s_a, PP, 0, 16, pk + (m0 >> 4) * 512, 512, lane, n0, gid, tig);

    float* yb = g_y1 + b * (NCn * Ln) + t0;
    #pragma unroll
    for (int mi = 0; mi < 2; mi++) {
        const int r0 = m0 + mi * 16 + gid;
        #pragma unroll
        for (int half = 0; half < 2; half++) {
            float* p = yb + (r0 + half * 8) * Ln + cb;
            *(float4*)(p)      = pick4(acc[mi], 0, half * 2);
            *(float4*)(p + 4)  = pick4(acc[mi], 4, half * 2);
            *(float4*)(p + 8)  = pick4(acc[mi], 0, half * 2 + 1);
            *(float4*)(p + 12) = pick4(acc[mi], 4, half * 2 + 1);
        }
    }
}

// ---------------------------------------------------------------------------
// post2: 512 threads, 16 warps (8M x 2N), tile 256co x 128t, K=256
// ---------------------------------------------------------------------------
constexpr int P2_SMEM = 256 * PP * 4;

__global__ __launch_bounds__(512, 1) void p2_kernel(const float* __restrict__ b2,
                                                    float* __restrict__ out)
{
    extern __shared__ unsigned smu[];
    unsigned* s_a = smu;
    const int b = blockIdx.y, t0 = blockIdx.x * 128, tid = threadIdx.x;

    const float* yb = g_y1 + b * (NCn * Ln);
    for (int i = tid; i < 256 * 32; i += 512) {
        const int ci = i >> 5, v = (i & 31) * 4;
        float4 x = *(const float4*)(yb + ci * Ln + t0 + v);
        uint4 s;
        s.x = f2tf(fmaxf(x.x, 0.0f)); s.y = f2tf(fmaxf(x.y, 0.0f));
        s.z = f2tf(fmaxf(x.z, 0.0f)); s.w = f2tf(fmaxf(x.w, 0.0f));
        *(uint4*)(s_a + ci * PP + v) = s;
    }
    __syncthreads();

    const int lane = tid & 31, warp = tid >> 5;
    const int gid = lane >> 2, tig = lane & 3;
    const int m0 = (warp & 7) * 32, n0 = (warp >> 3) * 64;
    const int cb = n0 + 16 * tig;

    float acc[2][8][4];
    #pragma unroll
    for (int mi = 0; mi < 2; mi++) {
        const int r0 = m0 + mi * 16 + gid;
        const float z0 = b2[r0], z1 = b2[r0 + 8];
        #pragma unroll
        for (int j = 0; j < 8; j++) {
            acc[mi][j][0] = z0; acc[mi][j][1] = z0;
            acc[mi][j][2] = z1; acc[mi][j][3] = z1;
        }
    }
    const uint4* pk = (const uint4*)(g_pk + OFF_P2);
    gemm_p2s(acc, s_a, PP, 0, 32, pk + (m0 >> 4) * 1024, 1024, lane, n0, gid, tig);

    float* ob = out + b * (NCn * Ln) + t0;
    #pragma unroll
    for (int mi = 0; mi < 2; mi++) {
        const int r0 = m0 + mi * 16 + gid;
        #pragma unroll
        for (int half = 0; half < 2; half++) {
            float* p = ob + (r0 + half * 8) * Ln + cb;
            *(float4*)(p)      = pick4(acc[mi], 0, half * 2);
            *(float4*)(p + 4)  = pick4(acc[mi], 4, half * 2);
            *(float4*)(p + 8)  = pick4(acc[mi], 0, half * 2 + 1);
            *(float4*)(p + 12) = pick4(acc[mi], 4, half * 2 + 1);
        }
    }
}

} // anonymous namespace

// ---------------------------------------------------------------------------
extern "C" void kernel_launch(void* const* d_in, const int* in_sizes, int n_in,
                              void* d_out, int out_size)
{
    (void)in_sizes; (void)n_in; (void)out_size;
    const float* x          = (const float*)d_in[0];
    const float* mels       = (const float*)d_in[1];
    const float* input_w    = (const float*)d_in[2];
    const float* input_b    = (const float*)d_in[3];
    const float* mel_w      = (const float*)d_in[4];
    const float* mel_b      = (const float*)d_in[5];
    const float* blk_dil_w  = (const float*)d_in[6];
    const float* blk_dil_b  = (const float*)d_in[7];
    const float* blk_cond_w = (const float*)d_in[8];
    const float* blk_cond_b = (const float*)d_in[9];
    const float* blk_skip_w = (const float*)d_in[10];
    const float* blk_skip_b = (const float*)d_in[11];
    const float* blk_res_w  = (const float*)d_in[12];
    const float* blk_res_b  = (const float*)d_in[13];
    const float* post1_w    = (const float*)d_in[14];
    const float* post1_b    = (const float*)d_in[15];
    const float* post2_w    = (const float*)d_in[16];
    const float* post2_b    = (const float*)d_in[17];

    cudaFuncSetAttribute(block_kernel, cudaFuncAttributeMaxDynamicSharedMemorySize, BLK_SMEM);
    cudaFuncSetAttribute(p1_kernel,    cudaFuncAttributeMaxDynamicSharedMemorySize, P1_SMEM);
    cudaFuncSetAttribute(p2_kernel,    cudaFuncAttributeMaxDynamicSharedMemorySize, P2_SMEM);

    float* resA; cudaGetSymbolAddress((void**)&resA, g_resA);
    float* resB; cudaGetSymbolAddress((void**)&resB, g_resB);

    prep_kernel<<<1024, 256>>>(blk_dil_w, blk_cond_w, blk_skip_w, blk_res_w,
                               post1_w, post2_w);
    cond_kernel<<<dim3(Ln / 128, Bn), 256>>>(mels, mel_w, mel_b);
    init_kernel<<<512, 256>>>(x, input_w, input_b);

    for (int i = 0; i < NBn; i++) {
        const float* rin  = (i & 1) ? resB : resA;
        float*       rout = (i & 1) ? resA : resB;
        block_kernel<<<dim3(Ln / 128, Bn), 256, BLK_SMEM>>>(
            blk_dil_b, blk_cond_b, blk_skip_b, blk_res_b, rin, rout, i);
    }

    p1_kernel<<<dim3(Ln / 128, Bn), 512, P1_SMEM>>>(post1_b);
    p2_kernel<<<dim3(Ln / 128, Bn), 512, P2_SMEM>>>(post2_b, (float*)d_out);
}

// round 6
// speedup vs baseline: 1.1062x; 1.1062x over previous
#include <cuda_runtime.h>

// ---------------------------------------------------------------------------
// WaveNet Mel2Raw — tf32 mma.sync, deferred-skip architecture:
//   30x block kernels: z-GEMM -> gate -> h (global, tf32 bits) + res update
//   1x tail kernel:    skip = sum_i Ws_i h_i (K=1920) -> relu -> p1 -> relu -> p2
// ---------------------------------------------------------------------------

namespace {

constexpr int Bn  = 2;
constexpr int Ln  = 32512;
constexpr int Rn  = 64;
constexpr int Sn  = 128;
constexpr int NMn = 80;
constexpr int NCn = 256;
constexpr int NBn = 30;

constexpr int AP = 136;   // smem pitch (x4B)

// ---- packed tf32 weight buffer (A fragments) ----
constexpr int PK_DIL_BLK  = 16384;
constexpr int PK_DIL_TAP  = 8192;
constexpr int OFF_DIL     = 0;
constexpr int PK_COND_BLK = 10240;
constexpr int OFF_COND    = 491520;
constexpr int PK_SKIP_BLK = 8192;
constexpr int OFF_SKIP    = 798720;
constexpr int PK_RES_BLK  = 4096;
constexpr int OFF_RES     = 1044480;
constexpr int OFF_P1      = 1167360;
constexpr int OFF_P2      = 1200128;
constexpr int PK_TOTAL    = 1265664;

__device__ unsigned g_pk[PK_TOTAL];
__device__ float    g_bs_sum[Sn];            // sum over layers of skip bias

__device__ float    g_cond[Bn * NMn * Ln];
__device__ float    g_resA[Bn * Rn  * Ln];
__device__ float    g_resB[Bn * Rn  * Ln];
__device__ unsigned g_h[NBn * Bn * Rn * Ln]; // tf32 bits, ~499 MB

__device__ __forceinline__ float ex2f(float x) {
    float y; asm("ex2.approx.f32 %0, %1;" : "=f"(y) : "f"(x)); return y;
}
__device__ __forceinline__ float rcpf(float x) {
    float y; asm("rcp.approx.f32 %0, %1;" : "=f"(y) : "f"(x)); return y;
}
__device__ __forceinline__ float gate_fn(float f, float g) {
    float ef = ex2f(2.8853900817779268f * f);
    float th = 1.0f - 2.0f * rcpf(ef + 1.0f);
    float sg = rcpf(1.0f + ex2f(-1.4426950408889634f * g));
    return th * sg;
}
__device__ __forceinline__ unsigned f2tf(float x) {
    unsigned u; asm("cvt.rna.tf32.f32 %0, %1;" : "=r"(u) : "f"(x)); return u;
}

__device__ __forceinline__ void mma8(float c[4], const unsigned a[4], const unsigned b[2]) {
    asm volatile(
        "mma.sync.aligned.m16n8k8.row.col.f32.tf32.tf32.f32 "
        "{%0,%1,%2,%3},{%4,%5,%6,%7},{%8,%9},{%0,%1,%2,%3};"
        : "+f"(c[0]), "+f"(c[1]), "+f"(c[2]), "+f"(c[3])
        : "r"(a[0]), "r"(a[1]), "r"(a[2]), "r"(a[3]), "r"(b[0]), "r"(b[1]));
}

// Two M-16 tiles (second at pkA + miStride), warp N tile = 64.
__device__ __forceinline__ void gemm_p2s(
    float acc[2][8][4], const unsigned* __restrict__ sB, int pitch,
    int rowbase, int nk, const uint4* __restrict__ pkA, int miStride,
    int lane, int n0, int gid, int tig)
{
    #pragma unroll
    for (int ks = 0; ks < nk; ks++) {
        uint4 va0 = pkA[ks * 32 + lane];
        uint4 va1 = pkA[miStride + ks * 32 + lane];
        unsigned A0[4] = {va0.x, va0.y, va0.z, va0.w};
        unsigned A1[4] = {va1.x, va1.y, va1.z, va1.w};
        const unsigned* b0 = sB + (rowbase + ks * 8 + tig) * pitch + n0 + gid;
        const unsigned* b1 = b0 + 4 * pitch;
        #pragma unroll
        for (int j = 0; j < 8; j++) {
            unsigned bf[2] = { b0[j * 8], b1[j * 8] };
            mma8(acc[0][j], A0, bf);
            mma8(acc[1][j], A1, bf);
        }
    }
}

// Single M-16 tile.
__device__ __forceinline__ void gemm_p1(
    float acc[8][4], const unsigned* __restrict__ sB, int pitch,
    int nk, const uint4* __restrict__ pkA,
    int lane, int n0, int gid, int tig)
{
    #pragma unroll
    for (int ks = 0; ks < nk; ks++) {
        uint4 va = pkA[ks * 32 + lane];
        unsigned A[4] = {va.x, va.y, va.z, va.w};
        const unsigned* b0 = sB + (ks * 8 + tig) * pitch + n0 + gid;
        const unsigned* b1 = b0 + 4 * pitch;
        #pragma unroll
        for (int j = 0; j < 8; j++) {
            unsigned bf[2] = { b0[j * 8], b1[j * 8] };
            mma8(acc[j], A, bf);
        }
    }
}

// ---------------------------------------------------------------------------
// prep: pack weights into tf32 A-fragment order + skip-bias sum
// ---------------------------------------------------------------------------
__device__ __forceinline__ uint4 pack_frag(const float* __restrict__ src,
                                           int as, int am, int ao,
                                           int nk, int idx4)
{
    const int mt   = idx4 / (nk * 32);
    const int rem  = idx4 % (nk * 32);
    const int ks   = rem >> 5;
    const int lane = rem & 31;
    const int gid  = lane >> 2, tig = lane & 3;
    const int r = mt * 16 + gid;
    const int k = ks * 8 + tig;
    uint4 v;
    v.x = f2tf(src[r * as + k * am + ao]);
    v.y = f2tf(src[(r + 8) * as + k * am + ao]);
    v.z = f2tf(src[r * as + (k + 4) * am + ao]);
    v.w = f2tf(src[(r + 8) * as + (k + 4) * am + ao]);
    return v;
}

__global__ void prep_kernel(
    const float* __restrict__ dil_w,  const float* __restrict__ cond_w,
    const float* __restrict__ skip_w, const float* __restrict__ res_w,
    const float* __restrict__ p1_w,   const float* __restrict__ p2_w,
    const float* __restrict__ skip_b)
{
    uint4* pk = (uint4*)g_pk;
    const int stride = gridDim.x * blockDim.x;
    const int g0 = blockIdx.x * blockDim.x + threadIdx.x;
    if (g0 < Sn) {
        float s = 0.0f;
        for (int i = 0; i < NBn; i++) s += skip_b[i * Sn + g0];
        g_bs_sum[g0] = s;
    }
    for (int q = g0; q < PK_TOTAL / 4; q += stride) {
        uint4 v;
        if (q < OFF_COND / 4) {
            const int blk = q / (PK_DIL_BLK / 4), r2 = q % (PK_DIL_BLK / 4);
            const int tap = r2 / (PK_DIL_TAP / 4), idx4 = r2 % (PK_DIL_TAP / 4);
            v = pack_frag(dil_w + blk * 16384, 128, 2, tap, 8, idx4);
        } else if (q < OFF_SKIP / 4) {
            const int q2 = q - OFF_COND / 4;
            const int blk = q2 / (PK_COND_BLK / 4), idx4 = q2 % (PK_COND_BLK / 4);
            v = pack_frag(cond_w + blk * (128 * NMn), NMn, 1, 0, 10, idx4);
        } else if (q < OFF_RES / 4) {
            const int q2 = q - OFF_SKIP / 4;
            const int blk = q2 / (PK_SKIP_BLK / 4), idx4 = q2 % (PK_SKIP_BLK / 4);
            v = pack_frag(skip_w + blk * (Sn * Rn), 64, 1, 0, 8, idx4);
        } else if (q < OFF_P1 / 4) {
            const int q2 = q - OFF_RES / 4;
            const int blk = q2 / (PK_RES_BLK / 4), idx4 = q2 % (PK_RES_BLK / 4);
            v = pack_frag(res_w + blk * (Rn * Rn), 64, 1, 0, 8, idx4);
        } else if (q < OFF_P2 / 4) {
            v = pack_frag(p1_w, 128, 1, 0, 16, q - OFF_P1 / 4);
        } else {
            v = pack_frag(p2_w, 256, 1, 0, 32, q - OFF_P2 / 4);
        }
        pk[q] = v;
    }
}

// ---------------------------------------------------------------------------
__global__ __launch_bounds__(256) void cond_kernel(
    const float* __restrict__ mels, const float* __restrict__ mel_w,
    const float* __restrict__ mel_b)
{
    __shared__ float m0s[NMn], m1s[NMn];
    const int b  = blockIdx.y;
    const int t0 = blockIdx.x * 128;
    const int q  = t0 >> 8;
    const int tid = threadIdx.x;
    if (tid < NMn) {
        m0s[tid] = mels[(b * NMn + tid) * 128 + q];
        m1s[tid] = mels[(b * NMn + tid) * 128 + q + 1];
    }
    __syncthreads();
    for (int j = tid; j < NMn * 128; j += 256) {
        const int c  = j >> 7;
        const int tt = j & 127;
        const int t  = t0 + tt;
        const int r  = t & 255;
        const float* w = mel_w + c * (NMn * 512);
        float acc = mel_b[c];
        #pragma unroll 4
        for (int ci = 0; ci < NMn; ci++) {
            acc += w[ci * 512 + 255 - r] * m0s[ci];
            acc += w[ci * 512 + 511 - r] * m1s[ci];
        }
        g_cond[(b * NMn + c) * Ln + t] = acc;
    }
}

__global__ void init_kernel(const float* __restrict__ x,
                            const float* __restrict__ iw,
                            const float* __restrict__ ib)
{
    const int stride = gridDim.x * blockDim.x;
    const int tid0   = blockIdx.x * blockDim.x + threadIdx.x;
    for (int i = tid0; i < Bn * Rn * Ln; i += stride) {
        const int t = i % Ln;
        const int r = (i / Ln) % Rn;
        const int b = i / (Ln * Rn);
        g_resA[i] = iw[r] * x[b * Ln + t] + ib[r];
    }
}

// ---------------------------------------------------------------------------
// Block kernel: z-GEMM (K=208) -> gate -> h (smem + global) -> res update
// 256 threads, 8 warps (4M x 2N), tile 128co x 128t
// ---------------------------------------------------------------------------
constexpr int BLK_SMEM = 208 * AP * 4;   // 113152 B -> 2 CTAs/SM

__global__ __launch_bounds__(256, 2) void block_kernel(
    const float* __restrict__ dil_b, const float* __restrict__ cond_b,
    const float* __restrict__ res_b,
    const float* __restrict__ res_in, float* __restrict__ res_out,
    int blk)
{
    extern __shared__ unsigned smu[];
    unsigned* s_act = smu;                 // rows: 0-63 prev, 64-127 cur, 128-207 cond
    unsigned* s_h   = smu;                 // rows 0-63 reused for h (tf32)

    const int d = 1 << (blk % 10);
    const float* bd = dil_b  + blk * 128;
    const float* bc = cond_b + blk * 128;
    const float* br = res_b  + blk * Rn;

    const int b   = blockIdx.y;
    const int t0  = blockIdx.x * 128;
    const int tid = threadIdx.x;

    // ---- stage activations ----
    const float* resb = res_in + b * (Rn * Ln);
    for (int i = tid; i < 64 * 128; i += 256) {
        const int ci = i >> 7, tt = i & 127;
        s_act[(64 + ci) * AP + tt] = f2tf(resb[ci * Ln + t0 + tt]);
        const int tp = t0 + tt - d;
        const float pv = (tp >= 0) ? resb[ci * Ln + tp] : 0.0f;
        s_act[ci * AP + tt] = f2tf(pv);
    }
    const float* condb = g_cond + b * (NMn * Ln);
    for (int i = tid; i < NMn * 128; i += 256) {
        const int ci = i >> 7, tt = i & 127;
        s_act[(128 + ci) * AP + tt] = f2tf(condb[ci * Ln + t0 + tt]);
    }
    __syncthreads();

    const int lane = tid & 31, warp = tid >> 5;
    const int gid = lane >> 2, tig = lane & 3;
    const int mw = warp & 3;
    const int n0 = (warp >> 2) * 64;
    const int m0f = mw * 16;

    // ---- GEMM1: acc[0] = f rows, acc[1] = g rows ----
    float acc[2][8][4];
    {
        const int rf = m0f + gid, rg = rf + 64;
        const float f0 = bd[rf] + bc[rf],       f1 = bd[rf + 8] + bc[rf + 8];
        const float g0 = bd[rg] + bc[rg],       g1 = bd[rg + 8] + bc[rg + 8];
        #pragma unroll
        for (int j = 0; j < 8; j++) {
            acc[0][j][0] = f0; acc[0][j][1] = f0; acc[0][j][2] = f1; acc[0][j][3] = f1;
            acc[1][j][0] = g0; acc[1][j][1] = g0; acc[1][j][2] = g1; acc[1][j][3] = g1;
        }
    }
    const uint4* pk_dil = (const uint4*)(g_pk + OFF_DIL + blk * PK_DIL_BLK);
    const uint4* pk_c   = (const uint4*)(g_pk + OFF_COND + blk * PK_COND_BLK);
    gemm_p2s(acc, s_act, AP,   0,  8, pk_dil + mw * 256,        4 * 256, lane, n0, gid, tig);
    gemm_p2s(acc, s_act, AP,  64,  8, pk_dil + 2048 + mw * 256, 4 * 256, lane, n0, gid, tig);
    gemm_p2s(acc, s_act, AP, 128, 10, pk_c + mw * 320,          4 * 320, lane, n0, gid, tig);

    __syncthreads();   // all GEMM1 smem reads complete

    // ---- gate in registers -> h (tf32) rows 0-63 ----
    {
        const int r0 = m0f + gid, r1 = r0 + 8;
        #pragma unroll
        for (int j = 0; j < 8; j++) {
            const int c = n0 + j * 8 + tig * 2;
            s_h[r0 * AP + c]     = f2tf(gate_fn(acc[0][j][0], acc[1][j][0]));
            s_h[r0 * AP + c + 1] = f2tf(gate_fn(acc[0][j][1], acc[1][j][1]));
            s_h[r1 * AP + c]     = f2tf(gate_fn(acc[0][j][2], acc[1][j][2]));
            s_h[r1 * AP + c + 1] = f2tf(gate_fn(acc[0][j][3], acc[1][j][3]));
        }
    }
    __syncthreads();

    // ---- write h to global (coalesced uint4), overlapped with GEMM3 ----
    {
        unsigned* ho = g_h + (size_t)(blk * Bn + b) * (Rn * Ln) + t0;
        for (int i = tid; i < 64 * 32; i += 256) {
            const int row = i >> 5, q = (i & 31) * 4;
            *(uint4*)(ho + row * Ln + q) = *(const uint4*)(s_h + row * AP + q);
        }
    }

    // ---- GEMM3: res_out = res_in + Wr*h + br (M=64, K=64) ----
    float accr[8][4];
    const int mr = mw * 16;
    {
        const int r0 = mr + gid;
        const float z0 = br[r0], z1 = br[r0 + 8];
        #pragma unroll
        for (int j = 0; j < 8; j++) {
            accr[j][0] = z0; accr[j][1] = z0;
            accr[j][2] = z1; accr[j][3] = z1;
        }
    }
    const uint4* pk_r = (const uint4*)(g_pk + OFF_RES + blk * PK_RES_BLK);
    gemm_p1(accr, s_h, AP, 8, pk_r + (mr >> 4) * 256, lane, n0, gid, tig);

    {
        float* rob = res_out + b * (Rn * Ln) + t0;
        const float* rib = resb + t0;
        const int r0 = mr + gid;
        #pragma unroll
        for (int j = 0; j < 8; j++) {
            const int c = n0 + j * 8 + tig * 2;
            rob[r0 * Ln + c]           = rib[r0 * Ln + c]           + accr[j][0];
            rob[r0 * Ln + c + 1]       = rib[r0 * Ln + c + 1]       + accr[j][1];
            rob[(r0 + 8) * Ln + c]     = rib[(r0 + 8) * Ln + c]     + accr[j][2];
            rob[(r0 + 8) * Ln + c + 1] = rib[(r0 + 8) * Ln + c + 1] + accr[j][3];
        }
    }
}

// ---------------------------------------------------------------------------
// Tail kernel: skip = bias_sum + sum_i Ws_i h_i (K=1920, double-buffered)
//              -> relu -> p1 (K=128) -> relu -> p2 (K=256) -> out
// 256 threads, 8 warps. Tile: 128 t.
// ---------------------------------------------------------------------------
constexpr int SP_SMEM = (128 * AP + 256 * AP) * 4;   // 208896 B

__global__ __launch_bounds__(256, 1) void sp_kernel(
    const float* __restrict__ b1, const float* __restrict__ b2,
    float* __restrict__ out)
{
    extern __shared__ unsigned smu[];
    unsigned* s_hb  = smu;                 // two h buffers [64][AP] each
    unsigned* s_sk  = smu;                 // reuse: relu(skip) tf32 [128][AP]
    unsigned* s_y1  = smu + 128 * AP;      // relu(y1) tf32 [256][AP]

    const int b   = blockIdx.y;
    const int t0  = blockIdx.x * 128;
    const int tid = threadIdx.x;
    const int lane = tid & 31, warp = tid >> 5;
    const int gid = lane >> 2, tig = lane & 3;
    const int mw = warp & 3;
    const int n0 = (warp >> 2) * 64;

    // ---- Phase A: skip accumulation over 30 layers ----
    const int m0s = mw * 32;
    float acc[2][8][4];
    {
        const int r0 = m0s + gid;
        const float z0 = g_bs_sum[r0],      z1 = g_bs_sum[r0 + 8];
        const float z2 = g_bs_sum[r0 + 16], z3 = g_bs_sum[r0 + 24];
        #pragma unroll
        for (int j = 0; j < 8; j++) {
            acc[0][j][0] = z0; acc[0][j][1] = z0; acc[0][j][2] = z1; acc[0][j][3] = z1;
            acc[1][j][0] = z2; acc[1][j][1] = z2; acc[1][j][2] = z3; acc[1][j][3] = z3;
        }
    }

    // preload h_0 into buffer 0
    {
        const unsigned* hp = g_h + (size_t)(0 * Bn + b) * (Rn * Ln) + t0;
        for (int i = tid; i < 64 * 32; i += 256) {
            const int row = i >> 5, q = (i & 31) * 4;
            *(uint4*)(s_hb + row * AP + q) = *(const uint4*)(hp + row * Ln + q);
        }
    }
    __syncthreads();

    const uint4* pk_s0 = (const uint4*)(g_pk + OFF_SKIP) + (m0s >> 4) * 256;
    for (int i = 0; i < NBn; i++) {
        // prefetch next layer's h into the other buffer
        if (i + 1 < NBn) {
            const unsigned* hp = g_h + (size_t)((i + 1) * Bn + b) * (Rn * Ln) + t0;
            unsigned* dst = s_hb + ((i + 1) & 1) * (64 * AP);
            for (int k = tid; k < 64 * 32; k += 256) {
                const int row = k >> 5, q = (k & 31) * 4;
                *(uint4*)(dst + row * AP + q) = *(const uint4*)(hp + row * Ln + q);
            }
        }
        gemm_p2s(acc, s_hb + (i & 1) * (64 * AP), AP, 0, 8,
                 pk_s0 + i * (PK_SKIP_BLK / 4), 256, lane, n0, gid, tig);
        __syncthreads();
    }

    // ---- Phase B: relu(skip) -> tf32 staging rows [128][AP] ----
    #pragma unroll
    for (int mi = 0; mi < 2; mi++) {
        const int r0 = m0s + mi * 16 + gid;
        #pragma unroll
        for (int j = 0; j < 8; j++) {
            const int c = n0 + j * 8 + tig * 2;
            s_sk[r0 * AP + c]           = f2tf(fmaxf(acc[mi][j][0], 0.0f));
            s_sk[r0 * AP + c + 1]       = f2tf(fmaxf(acc[mi][j][1], 0.0f));
            s_sk[(r0 + 8) * AP + c]     = f2tf(fmaxf(acc[mi][j][2], 0.0f));
            s_sk[(r0 + 8) * AP + c + 1] = f2tf(fmaxf(acc[mi][j][3], 0.0f));
        }
    }
    __syncthreads();

    // ---- Phase C: p1 (M=256, K=128) -> relu -> tf32 staging s_y1 ----
    const int m0p = warp * 32;   // 8 warps x 32 = 256 rows
    const uint4* pkP1 = (const uint4*)(g_pk + OFF_P1) + (m0p >> 4) * 512;
    #pragma unroll
    for (int nh = 0; nh < 2; nh++) {
        const int nn = nh * 64;
        {
            const int r0 = m0p + gid;
            const float z0 = b1[r0], z1 = b1[r0 + 8];
            const float z2 = b1[r0 + 16], z3 = b1[r0 + 24];
            #pragma unroll
            for (int j = 0; j < 8; j++) {
                acc[0][j][0] = z0; acc[0][j][1] = z0; acc[0][j][2] = z1; acc[0][j][3] = z1;
                acc[1][j][0] = z2; acc[1][j][1] = z2; acc[1][j][2] = z3; acc[1][j][3] = z3;
            }
        }
        gemm_p2s(acc, s_sk, AP, 0, 16, pkP1, 512, lane, nn, gid, tig);
        #pragma unroll
        for (int mi = 0; mi < 2; mi++) {
            const int r0 = m0p + mi * 16 + gid;
            #pragma unroll
            for (int j = 0; j < 8; j++) {
                const int c = nn + j * 8 + tig * 2;
                s_y1[r0 * AP + c]           = f2tf(fmaxf(acc[mi][j][0], 0.0f));
                s_y1[r0 * AP + c + 1]       = f2tf(fmaxf(acc[mi][j][1], 0.0f));
                s_y1[(r0 + 8) * AP + c]     = f2tf(fmaxf(acc[mi][j][2], 0.0f));
                s_y1[(r0 + 8) * AP + c + 1] = f2tf(fmaxf(acc[mi][j][3], 0.0f));
            }
        }
    }
    __syncthreads();

    // ---- Phase D: p2 (M=256, K=256) -> out ----
    const uint4* pkP2 = (const uint4*)(g_pk + OFF_P2) + (m0p >> 4) * 1024;
    float* ob = out + (size_t)b * (NCn * Ln) + t0;
    #pragma unroll
    for (int nh = 0; nh < 2; nh++) {
        const int nn = nh * 64;
        {
            const int r0 = m0p + gid;
            const float z0 = b2[r0], z1 = b2[r0 + 8];
            const float z2 = b2[r0 + 16], z3 = b2[r0 + 24];
            #pragma unroll
            for (int j = 0; j < 8; j++) {
                acc[0][j][0] = z0; acc[0][j][1] = z0; acc[0][j][2] = z1; acc[0][j][3] = z1;
                acc[1][j][0] = z2; acc[1][j][1] = z2; acc[1][j][2] = z3; acc[1][j][3] = z3;
            }
        }
        gemm_p2s(acc, s_y1, AP, 0, 32, pkP2, 1024, lane, nn, gid, tig);
        #pragma unroll
        for (int mi = 0; mi < 2; mi++) {
            const int r0 = m0p + mi * 16 + gid;
            #pragma unroll
            for (int j = 0; j < 8; j++) {
                const int c = nn + j * 8 + tig * 2;
                float* p = ob + r0 * Ln + c;
                p[0] = acc[mi][j][0]; p[1] = acc[mi][j][1];
                float* q = ob + (r0 + 8) * Ln + c;
                q[0] = acc[mi][j][2]; q[1] = acc[mi][j][3];
            }
        }
    }
}

} // anonymous namespace

// ---------------------------------------------------------------------------
extern "C" void kernel_launch(void* const* d_in, const int* in_sizes, int n_in,
                              void* d_out, int out_size)
{
    (void)in_sizes; (void)n_in; (void)out_size;
    const float* x          = (const float*)d_in[0];
    const float* mels       = (const float*)d_in[1];
    const float* input_w    = (const float*)d_in[2];
    const float* input_b    = (const float*)d_in[3];
    const float* mel_w      = (const float*)d_in[4];
    const float* mel_b      = (const float*)d_in[5];
    const float* blk_dil_w  = (const float*)d_in[6];
    const float* blk_dil_b  = (const float*)d_in[7];
    const float* blk_cond_w = (const float*)d_in[8];
    const float* blk_cond_b = (const float*)d_in[9];
    const float* blk_skip_w = (const float*)d_in[10];
    const float* blk_skip_b = (const float*)d_in[11];
    const float* blk_res_w  = (const float*)d_in[12];
    const float* blk_res_b  = (const float*)d_in[13];
    const float* post1_w    = (const float*)d_in[14];
    const float* post1_b    = (const float*)d_in[15];
    const float* post2_w    = (const float*)d_in[16];
    const float* post2_b    = (const float*)d_in[17];

    cudaFuncSetAttribute(block_kernel, cudaFuncAttributeMaxDynamicSharedMemorySize, BLK_SMEM);
    cudaFuncSetAttribute(sp_kernel,    cudaFuncAttributeMaxDynamicSharedMemorySize, SP_SMEM);

    float* resA; cudaGetSymbolAddress((void**)&resA, g_resA);
    float* resB; cudaGetSymbolAddress((void**)&resB, g_resB);

    prep_kernel<<<1024, 256>>>(blk_dil_w, blk_cond_w, blk_skip_w, blk_res_w,
                               post1_w, post2_w, blk_skip_b);
    cond_kernel<<<dim3(Ln / 128, Bn), 256>>>(mels, mel_w, mel_b);
    init_kernel<<<512, 256>>>(x, input_w, input_b);

    for (int i = 0; i < NBn; i++) {
        const float* rin  = (i & 1) ? resB : resA;
        float*       rout = (i & 1) ? resA : resB;
        block_kernel<<<dim3(Ln / 128, Bn), 256, BLK_SMEM>>>(
            blk_dil_b, blk_cond_b, blk_res_b, rin, rout, i);
    }

    sp_kernel<<<dim3(Ln / 128, Bn), 256, SP_SMEM>>>(post1_b, post2_b, (float*)d_out);
}